// round 10
// baseline (speedup 1.0000x reference)
#include <cuda_runtime.h>
#include <math.h>
#include <stdint.h>

#define BATCH 64
#define NPTS  512
#define DIM   512
#define NIDS  32                       // track ids are in [-1, 32)
#define DTHREADS 128
#define DWARPS 4
#define IDBLOCKS (BATCH * NIDS)        // 2048: one block per (batch, id)
#define F4 (DIM / 4)                   // 128 float4 per row

__device__ __constant__ float c_margin = 0.3f;
__device__ __constant__ float c_eps    = 1e-6f;

// scratch (no allocations allowed) — zero-initialized; last block resets.
__device__ float        g_tot;
__device__ int          g_cntall;
__device__ unsigned int g_ticket;

// 16B async copy, L2-only (.cg): streamed anchor rows shouldn't pollute L1.
__device__ __forceinline__ void cp_async16(uint32_t smem_dst, const float4* gsrc) {
    asm volatile("cp.async.cg.shared.global [%0], [%1], 16;"
                 :: "r"(smem_dst), "l"(gsrc));
}
#define CP_COMMIT()     asm volatile("cp.async.commit_group;" ::)
#define CP_WAIT1()      asm volatile("cp.async.wait_group 1;" ::)

// accumulate |a4-q4+eps|^2 into acc
#define ACC4(a4, q4, acc)                                    \
    do {                                                     \
        float d_;                                            \
        d_ = (a4).x - (q4).x + eps; acc = fmaf(d_, d_, acc); \
        d_ = (a4).y - (q4).y + eps; acc = fmaf(d_, d_, acc); \
        d_ = (a4).z - (q4).z + eps; acc = fmaf(d_, d_, acc); \
        d_ = (a4).w - (q4).w + eps; acc = fmaf(d_, d_, acc); \
    } while (0)

// ---------------------------------------------------------------------------
// R10: (batch,id) blocks for minimal traffic (shared pos/pos2/neg rows staged
// once), plus a per-warp depth-2 cp.async pipeline on anchor rows so MLP
// lives in SMEM commit-groups instead of registers (R5-R9 showed ptxas caps
// register-resident MLP; all designs plateaued 21-23us).
//
// Closed-form replacement for argmax-of-mask (ids in [-1, 32)):
//   pos(i) = first[m] != i ? first[m] : second[m]     (needs count[m] >= 2)
//   neg(i) = ids[j1] != m ? j1 : j2                   (needs nvalid > count[m])
// Each lane stages and consumes the same smem slots -> no warp sync needed
// around the per-thread cp.async groups.
// ---------------------------------------------------------------------------
__global__ void __launch_bounds__(DTHREADS)
dist_kernel(const float* __restrict__ feats,
            const int*   __restrict__ ids,
            float*       __restrict__ out,
            int out_size)
{
    const int blk  = blockIdx.x;
    const int b    = blk >> 5;           // batch
    const int myid = blk & 31;           // track id this block owns
    const int t    = threadIdx.x;
    const int wid  = t >> 5;
    const int lane = t & 31;

    __shared__ float4 s_anc[DWARPS][2][F4];   // per-warp double buffer (16KB)
    __shared__ float4 s_pos[F4];              // row `first`
    __shared__ float4 s_pos2[F4];             // row `second`
    __shared__ float4 s_neg[F4];              // the block's negative row
    __shared__ int s_list[NPTS];
    __shared__ int s_first, s_second, s_j1, s_j2, s_idj1;
    __shared__ int s_n, s_nv, s_cm;
    __shared__ float s_tot;
    __shared__ int   s_cnt;

    if (t == 0) {
        s_first = 0x7fffffff; s_second = 0x7fffffff;
        s_j1 = 0x7fffffff;    s_j2 = 0x7fffffff;
        s_n = 0; s_nv = 0; s_cm = 0;
        s_tot = 0.0f; s_cnt = 0;
    }
    __syncthreads();

    const int* __restrict__ bid = ids + b * NPTS;

    // Pass 1: one int4 per thread covers all 512 ids.
    const int4 iv = ((const int4*)bid)[t];
    const int idr[4] = { iv.x, iv.y, iv.z, iv.w };
    int lv = 0, lm = 0;
    #pragma unroll
    for (int r = 0; r < 4; ++r) {
        const int i = 4 * t + r;
        if (idr[r] >= 0) {
            lv++;
            atomicMin(&s_j1, i);
            if (idr[r] == myid) { lm++; atomicMin(&s_first, i); }
        }
    }
    #pragma unroll
    for (int o = 16; o > 0; o >>= 1) {
        lv += __shfl_xor_sync(0xFFFFFFFFu, lv, o);
        lm += __shfl_xor_sync(0xFFFFFFFFu, lm, o);
    }
    if (lane == 0) { atomicAdd(&s_nv, lv); atomicAdd(&s_cm, lm); }
    __syncthreads();
    if (t == 0) s_idj1 = (s_j1 < NPTS) ? bid[s_j1] : -2;
    __syncthreads();

    // Pass 2: second occurrence; first valid with id != ids[j1]; anchor list.
    const int first = s_first;
    const int idj1  = s_idj1;
    #pragma unroll
    for (int r = 0; r < 4; ++r) {
        const int i = 4 * t + r;
        if (idr[r] == myid) {
            if (i != first) atomicMin(&s_second, i);
            const int k = atomicAdd(&s_n, 1);
            s_list[k] = i;
        }
        if (idr[r] >= 0 && idr[r] != idj1) atomicMin(&s_j2, i);
    }
    __syncthreads();

    const int cm = s_cm;
    const int nv = s_nv;
    const bool ok = (cm >= 2) && (nv > cm);

    float w_tot = 0.0f;
    int   w_cnt = 0;

    if (ok) {
        const int second = s_second;
        const int nidx   = (idj1 != myid) ? s_j1 : s_j2;
        const float4* __restrict__ base4 =
            (const float4*)(feats + (size_t)b * NPTS * DIM);
        const float eps = c_eps;

        // Stage the 3 shared rows (block-cooperative, one f4 per thread per row).
        {
            const float4* __restrict__ fP = base4 + (size_t)first  * F4;
            const float4* __restrict__ fS = base4 + (size_t)second * F4;
            const float4* __restrict__ fN = base4 + (size_t)nidx   * F4;
            s_pos [t] = fP[t];
            s_pos2[t] = fS[t];
            s_neg [t] = fN[t];
        }
        __syncthreads();

        // Per-warp depth-2 cp.async pipeline over this warp's anchors.
        const int nA = (cm > wid) ? ((cm - wid + DWARPS - 1) / DWARPS) : 0;
        const uint32_t anc0 = (uint32_t)__cvta_generic_to_shared(&s_anc[wid][0][0]);
        const uint32_t anc1 = (uint32_t)__cvta_generic_to_shared(&s_anc[wid][1][0]);

        // stage anchor j's row into buffer buf (4 x 16B per lane)
        #define STAGE(j, bufaddr)                                             \
            do {                                                              \
                const int i_ = s_list[wid + (j) * DWARPS];                    \
                const float4* src_ = base4 + (size_t)i_ * F4;                 \
                _Pragma("unroll")                                             \
                for (int k_ = 0; k_ < 4; ++k_)                                \
                    cp_async16((bufaddr) + (uint32_t)((k_ * 32 + lane) * 16), \
                               src_ + k_ * 32 + lane);                        \
            } while (0)

        if (nA > 0) STAGE(0, anc0);
        CP_COMMIT();
        if (nA > 1) STAGE(1, anc1);
        CP_COMMIT();

        for (int j = 0; j < nA; ++j) {
            CP_WAIT1();                          // buffer j%2 is ready
            const int i = s_list[wid + j * DWARPS];
            const float4* __restrict__ pb = (i == first) ? s_pos2 : s_pos;
            const float4* __restrict__ ab = s_anc[wid][j & 1];

            float sap = 0.0f, san = 0.0f;
            #pragma unroll
            for (int k = 0; k < 4; ++k) {
                const float4 a4 = ab[k * 32 + lane];
                ACC4(a4, pb[k * 32 + lane], sap);
                ACC4(a4, s_neg[k * 32 + lane], san);
            }
            #pragma unroll
            for (int o = 16; o > 0; o >>= 1) {
                sap += __shfl_xor_sync(0xFFFFFFFFu, sap, o);
                san += __shfl_xor_sync(0xFFFFFFFFu, san, o);
            }
            if (lane == 0) {
                const float per = sqrtf(sap) - sqrtf(san) + c_margin;
                if (per > 0.0f) w_tot += per;
                w_cnt++;
            }
            if (j + 2 < nA) STAGE(j + 2, (j & 1) ? anc1 : anc0);
            CP_COMMIT();                         // one group per iteration
        }
        #undef STAGE
    }

    if (lane == 0) {
        atomicAdd(&s_tot, w_tot);
        atomicAdd(&s_cnt, w_cnt);
    }
    __syncthreads();

    if (t == 0) {
        atomicAdd(&g_tot, s_tot);
        atomicAdd(&g_cntall, s_cnt);
        __threadfence();
        const unsigned int old = atomicAdd(&g_ticket, 1u);
        if (old == IDBLOCKS - 1) {
            __threadfence();                 // see all blocks' adds
            const float T = g_tot;
            const int   C = g_cntall;
            const float loss = (C > 0) ? (T / (float)C) : 0.0f;
            if (out_size > 0) out[0] = loss; // tracking_loss
            if (out_size > 1) out[1] = loss; // loss_triplet
            if (out_size > 2) out[2] = 0.0f; // loss_id
            g_tot    = 0.0f;                 // reset for next graph replay
            g_cntall = 0;
            g_ticket = 0;
            __threadfence();
        }
    }
}

extern "C" void kernel_launch(void* const* d_in, const int* in_sizes, int n_in,
                              void* d_out, int out_size)
{
    const float* feats = (const float*)d_in[0];
    const int*   ids   = (const int*)d_in[1];
    float*       out   = (float*)d_out;

    dist_kernel<<<IDBLOCKS, DTHREADS>>>(feats, ids, out, out_size);
}

// round 11
// speedup vs baseline: 1.0980x; 1.0980x over previous
#include <cuda_runtime.h>
#include <math.h>
#include <stdint.h>

#define BATCH 64
#define NPTS  512
#define DIM   512
#define NIDS  32                        // track ids are in [-1, 32)
#define IDS_PER_BLK 4
#define BPB  (NIDS / IDS_PER_BLK)       // 8 blocks per batch
#define GRID (BATCH * BPB)              // 512 blocks -> single wave at 4/SM
#define DTHREADS 256
#define DWARPS 8
#define F4 (DIM / 4)                    // 128 float4 per row

__device__ __constant__ float c_margin = 0.3f;
__device__ __constant__ float c_eps    = 1e-6f;

// scratch (no allocations allowed) — zero-initialized; last block resets.
__device__ float        g_tot;
__device__ int          g_cntall;
__device__ unsigned int g_ticket;

// 16B async copy, L2-only (.cg): streamed anchor rows shouldn't pollute L1.
__device__ __forceinline__ void cp_async16(uint32_t smem_dst, const float4* gsrc) {
    asm volatile("cp.async.cg.shared.global [%0], [%1], 16;"
                 :: "r"(smem_dst), "l"(gsrc));
}
#define CP_COMMIT()     asm volatile("cp.async.commit_group;" ::)
#define CP_WAIT1()      asm volatile("cp.async.wait_group 1;" ::)

// accumulate |a4-q4+eps|^2 into acc
#define ACC4(a4, q4, acc)                                    \
    do {                                                     \
        float d_;                                            \
        d_ = (a4).x - (q4).x + eps; acc = fmaf(d_, d_, acc); \
        d_ = (a4).y - (q4).y + eps; acc = fmaf(d_, d_, acc); \
        d_ = (a4).z - (q4).z + eps; acc = fmaf(d_, d_, acc); \
        d_ = (a4).w - (q4).w + eps; acc = fmaf(d_, d_, acc); \
    } while (0)

// ---------------------------------------------------------------------------
// R11: 4 ids per block (512 blocks, one wave at 4 blocks/SM), full 32-id
// table prologue amortized over ~64 anchors, 6 shared rows staged in smem
// (4 pos + the batch's 2 negative candidates), and a per-warp depth-2
// cp.async pipeline over ~8 anchors/warp. Keeps R10's traffic minimum while
// fixing its granularity (R10: 2048 blocks x 4-anchor warps left the
// pipeline in its prologue).
//
// Closed-form replacement for argmax-of-mask (ids in [-1, 32)):
//   pos(i) = first[m] != i ? first[m] : second[m]     (needs count[m] >= 2)
//   neg(i) = ids[j1] != m ? j1 : j2                   (needs nvalid > count[m])
// ---------------------------------------------------------------------------
__global__ void __launch_bounds__(DTHREADS)
dist_kernel(const float* __restrict__ feats,
            const int*   __restrict__ ids,
            float*       __restrict__ out,
            int out_size)
{
    const int blk  = blockIdx.x;
    const int b    = blk >> 3;                 // batch
    const int idbase = (blk & 7) * IDS_PER_BLK;
    const int t    = threadIdx.x;
    const int wid  = t >> 5;
    const int lane = t & 31;

    __shared__ float4 s_anc[DWARPS][2][F4];    // per-warp double buffer (32KB)
    __shared__ float4 s_rows[6][F4];           // 4 pos rows + j1 row + j2 row (12KB)
    __shared__ int s_li[NPTS];                 // packed anchor list: i | (c<<16)
    __shared__ int s_first[NIDS];
    __shared__ int s_second[NIDS];
    __shared__ int s_count[NIDS];
    __shared__ int s_j1, s_j2, s_idj1, s_nvalid, s_n;
    __shared__ float s_tot;
    __shared__ int   s_cnt;

    if (t < NIDS) {
        s_first[t]  = 0x7fffffff;
        s_second[t] = 0x7fffffff;
        s_count[t]  = 0;
    }
    if (t == 0) {
        s_j1 = 0x7fffffff; s_j2 = 0x7fffffff;
        s_nvalid = 0; s_n = 0;
        s_tot = 0.0f; s_cnt = 0;
    }
    __syncthreads();

    const int* __restrict__ bid = ids + b * NPTS;

    // Pass 1: first occurrence per id, per-id counts, first valid overall.
    const int i0  = t;
    const int i1  = t + DTHREADS;
    const int id0 = bid[i0];
    const int id1 = bid[i1];
    if (id0 >= 0) {
        atomicMin(&s_first[id0], i0);
        atomicAdd(&s_count[id0], 1);
        atomicMin(&s_j1, i0);
    }
    if (id1 >= 0) {
        atomicMin(&s_first[id1], i1);
        atomicAdd(&s_count[id1], 1);
        atomicMin(&s_j1, i1);
    }
    int nv = __syncthreads_count(id0 >= 0);
    nv    += __syncthreads_count(id1 >= 0);
    if (t == 0) {
        s_nvalid = nv;
        s_idj1 = (s_j1 < NPTS) ? bid[s_j1] : -2;
    }
    __syncthreads();

    // Pass 2: second occurrence per id; first valid with id != ids[j1].
    const int idj1 = s_idj1;
    if (id0 >= 0) {
        if (i0 != s_first[id0]) atomicMin(&s_second[id0], i0);
        if (id0 != idj1)        atomicMin(&s_j2, i0);
    }
    if (id1 >= 0) {
        if (i1 != s_first[id1]) atomicMin(&s_second[id1], i1);
        if (id1 != idj1)        atomicMin(&s_j2, i1);
    }
    __syncthreads();

    const int nvalid = s_nvalid;

    // Which of my 4 ids produce valid triplets?
    // ok(id m): count[m] >= 2 && nvalid > count[m]
    // Pass 3: compact anchor list for my ok ids (order nondeterministic;
    // fp sum order varies ~1e-7, tolerance is 1e-3).
    {
        const int m0 = (id0 >= 0 && id0 >= idbase && id0 < idbase + IDS_PER_BLK) ? id0 : -1;
        const int m1 = (id1 >= 0 && id1 >= idbase && id1 < idbase + IDS_PER_BLK) ? id1 : -1;
        if (m0 >= 0 && s_count[m0] >= 2 && nvalid > s_count[m0]) {
            const int k = atomicAdd(&s_n, 1);
            s_li[k] = i0 | ((m0 - idbase) << 16);
        }
        if (m1 >= 0 && s_count[m1] >= 2 && nvalid > s_count[m1]) {
            const int k = atomicAdd(&s_n, 1);
            s_li[k] = i1 | ((m1 - idbase) << 16);
        }
    }
    __syncthreads();

    const int n = s_n;

    float w_tot = 0.0f;
    int   w_cnt = 0;

    const float4* __restrict__ base4 =
        (const float4*)(feats + (size_t)b * NPTS * DIM);
    const float eps = c_eps;

    if (n > 0) {
        // Stage 6 shared rows: pos rows (first of each of my 4 ids) + j1 + j2.
        // Clamp unused/invalid indices to 0 (never read in that case).
        {
            int rowidx[6];
            #pragma unroll
            for (int c = 0; c < IDS_PER_BLK; ++c) {
                const int f = s_first[idbase + c];
                rowidx[c] = (f < NPTS) ? f : 0;
            }
            rowidx[4] = (s_j1 < NPTS) ? s_j1 : 0;
            rowidx[5] = (s_j2 < NPTS) ? s_j2 : 0;
            // 6 rows x 128 f4 = 768 f4; 256 threads -> 3 each
            #pragma unroll
            for (int r = 0; r < 3; ++r) {
                const int e   = t + r * DTHREADS;   // 0..767
                const int row = e >> 7;             // 0..5
                const int col = e & 127;
                s_rows[row][col] = base4[(size_t)rowidx[row] * F4 + col];
            }
        }
        __syncthreads();

        // Per-warp depth-2 cp.async pipeline over list slots wid, wid+8, ...
        const uint32_t anc0 = (uint32_t)__cvta_generic_to_shared(&s_anc[wid][0][0]);
        const uint32_t anc1 = (uint32_t)__cvta_generic_to_shared(&s_anc[wid][1][0]);

        #define STAGE(slot, bufaddr)                                          \
            do {                                                              \
                const int i_ = s_li[slot] & 0xFFFF;                           \
                const float4* src_ = base4 + (size_t)i_ * F4;                 \
                _Pragma("unroll")                                             \
                for (int k_ = 0; k_ < 4; ++k_)                                \
                    cp_async16((bufaddr) + (uint32_t)((k_ * 32 + lane) * 16), \
                               src_ + k_ * 32 + lane);                        \
            } while (0)

        if (wid < n)            STAGE(wid, anc0);
        CP_COMMIT();
        if (wid + DWARPS < n)   STAGE(wid + DWARPS, anc1);
        CP_COMMIT();

        int buf = 0;
        for (int slot = wid; slot < n; slot += DWARPS, buf ^= 1) {
            CP_WAIT1();                          // current buffer ready
            const int pk = s_li[slot];
            const int i  = pk & 0xFFFF;
            const int c  = pk >> 16;
            const int m  = idbase + c;
            const float4* __restrict__ ab = s_anc[wid][buf];
            const int nb = (idj1 != m) ? 4 : 5;  // negative row buffer

            float sap = 0.0f, san = 0.0f;
            if (i != s_first[m]) {
                // common path: pos row staged in smem
                const float4* __restrict__ pb = s_rows[c];
                const float4* __restrict__ ng = s_rows[nb];
                #pragma unroll
                for (int k = 0; k < 4; ++k) {
                    const float4 a4 = ab[k * 32 + lane];
                    ACC4(a4, pb[k * 32 + lane], sap);
                    ACC4(a4, ng[k * 32 + lane], san);
                }
            } else {
                // the anchor that IS `first` pairs with `second` (global)
                const float4* __restrict__ pg =
                    base4 + (size_t)s_second[m] * F4;
                const float4* __restrict__ ng = s_rows[nb];
                #pragma unroll
                for (int k = 0; k < 4; ++k) {
                    const float4 a4 = ab[k * 32 + lane];
                    ACC4(a4, pg[k * 32 + lane], sap);
                    ACC4(a4, ng[k * 32 + lane], san);
                }
            }

            #pragma unroll
            for (int o = 16; o > 0; o >>= 1) {
                sap += __shfl_xor_sync(0xFFFFFFFFu, sap, o);
                san += __shfl_xor_sync(0xFFFFFFFFu, san, o);
            }
            if (lane == 0) {
                const float per = sqrtf(sap) - sqrtf(san) + c_margin;
                if (per > 0.0f) w_tot += per;
                w_cnt++;
            }

            if (slot + 2 * DWARPS < n) STAGE(slot + 2 * DWARPS, buf ? anc1 : anc0);
            CP_COMMIT();                         // one group per iteration
        }
        #undef STAGE
    }

    if (lane == 0) {
        atomicAdd(&s_tot, w_tot);
        atomicAdd(&s_cnt, w_cnt);
    }
    __syncthreads();

    if (t == 0) {
        atomicAdd(&g_tot, s_tot);
        atomicAdd(&g_cntall, s_cnt);
        __threadfence();
        const unsigned int old = atomicAdd(&g_ticket, 1u);
        if (old == GRID - 1) {
            __threadfence();                 // see all blocks' adds
            const float T = g_tot;
            const int   C = g_cntall;
            const float loss = (C > 0) ? (T / (float)C) : 0.0f;
            if (out_size > 0) out[0] = loss; // tracking_loss
            if (out_size > 1) out[1] = loss; // loss_triplet
            if (out_size > 2) out[2] = 0.0f; // loss_id
            g_tot    = 0.0f;                 // reset for next graph replay
            g_cntall = 0;
            g_ticket = 0;
            __threadfence();
        }
    }
}

extern "C" void kernel_launch(void* const* d_in, const int* in_sizes, int n_in,
                              void* d_out, int out_size)
{
    const float* feats = (const float*)d_in[0];
    const int*   ids   = (const int*)d_in[1];
    float*       out   = (float*)d_out;

    dist_kernel<<<GRID, DTHREADS>>>(feats, ids, out, out_size);
}

// round 12
// speedup vs baseline: 1.1115x; 1.0122x over previous
#include <cuda_runtime.h>
#include <math.h>
#include <stdint.h>

#define BATCH 64
#define NPTS  512
#define DIM   512
#define NIDS  32                        // track ids are in [-1, 32)
#define IDS_PER_BLK 4
#define GRID  (BATCH * (NIDS / IDS_PER_BLK))   // 512 blocks, single wave
#define DTHREADS 128
#define DWARPS 4                        // warp w owns id idbase+w
#define F4 (DIM / 4)                    // 128 float4 per row

__device__ __constant__ float c_margin = 0.3f;
__device__ __constant__ float c_eps    = 1e-6f;

// scratch (no allocations allowed) — zero-initialized; last block resets.
__device__ float        g_tot;
__device__ int          g_cntall;
__device__ unsigned int g_ticket;

// 16B async copy, L2-only (.cg): streamed anchor rows bypass L1.
__device__ __forceinline__ void cp_async16(uint32_t smem_dst, const float4* gsrc) {
    asm volatile("cp.async.cg.shared.global [%0], [%1], 16;"
                 :: "r"(smem_dst), "l"(gsrc));
}
#define CP_COMMIT() asm volatile("cp.async.commit_group;" ::)
#define CP_WAIT1()  asm volatile("cp.async.wait_group 1;" ::)

// identity form: a' = a+eps; sap += a'*(a'-2P); san += a'*(a'-2N)
// (sap_total + |P|^2 == sum((a-p+eps)^2), exact per element)
#define ACCC(av, Pv, Nv, sap, san)               \
    do {                                         \
        const float a_ = (av) + eps;             \
        float t_ = fmaf(-2.0f, (Pv), a_);        \
        sap = fmaf(a_, t_, sap);                 \
        t_ = fmaf(-2.0f, (Nv), a_);              \
        san = fmaf(a_, t_, san);                 \
    } while (0)
#define ACCK(a4, P4, N4, sap, san)                    \
    do {                                              \
        ACCC((a4).x, (P4).x, (N4).x, sap, san);       \
        ACCC((a4).y, (P4).y, (N4).y, sap, san);       \
        ACCC((a4).z, (P4).z, (N4).z, sap, san);       \
        ACCC((a4).w, (P4).w, (N4).w, sap, san);       \
    } while (0)
// pos-only form for the rare `anchor == first` recompute against `second`
#define ACCP1(av, Pv, sap)                            \
    do {                                              \
        const float a_ = (av) + eps;                  \
        const float t_ = fmaf(-2.0f, (Pv), a_);       \
        sap = fmaf(a_, t_, sap);                      \
    } while (0)
#define ACCPK(a4, P4, sap)                            \
    do {                                              \
        ACCP1((a4).x, (P4).x, sap);                   \
        ACCP1((a4).y, (P4).y, sap);                   \
        ACCP1((a4).z, (P4).z, sap);                   \
        ACCP1((a4).w, (P4).w, sap);                   \
    } while (0)
#define NRM4(v, acc)                                  \
    do {                                              \
        acc = fmaf((v).x, (v).x, acc);                \
        acc = fmaf((v).y, (v).y, acc);                \
        acc = fmaf((v).z, (v).z, acc);                \
        acc = fmaf((v).w, (v).w, acc);                \
    } while (0)

// ---------------------------------------------------------------------------
// R12: one id per warp; the warp's pos/neg rows live in REGISTERS (with
// pre-reduced norms), so the inner loop touches smem only for the anchor row
// (4 LDS.128/anchor vs R11's 12). Anchor pairs staged via depth-2 cp.async.
// Distance via sum(a'(a'-2P)) + |P|^2 identity (exact; a'=a+eps).
// ---------------------------------------------------------------------------
__global__ void __launch_bounds__(DTHREADS)
dist_kernel(const float* __restrict__ feats,
            const int*   __restrict__ ids,
            float*       __restrict__ out,
            int out_size)
{
    const int blk    = blockIdx.x;
    const int b      = blk >> 3;                // batch
    const int idbase = (blk & 7) * IDS_PER_BLK;
    const int t      = threadIdx.x;
    const int wid    = t >> 5;
    const int lane   = t & 31;

    __shared__ float4 s_anc[DWARPS][2][2][F4];  // warp / buf / pair-slot (32KB)
    __shared__ int s_list[NPTS];                // grouped by id
    __shared__ int s_first[NIDS];
    __shared__ int s_second[NIDS];
    __shared__ int s_count[NIDS];
    __shared__ int s_sub[IDS_PER_BLK];
    __shared__ int s_j1, s_j2, s_idj1, s_nvalid;
    __shared__ float s_tot;
    __shared__ int   s_cnt;

    if (t < NIDS) {
        s_first[t]  = 0x7fffffff;
        s_second[t] = 0x7fffffff;
        s_count[t]  = 0;
    }
    if (t < IDS_PER_BLK) s_sub[t] = 0;
    if (t == 0) {
        s_j1 = 0x7fffffff; s_j2 = 0x7fffffff;
        s_nvalid = 0; s_tot = 0.0f; s_cnt = 0;
    }
    __syncthreads();

    const int* __restrict__ bid = ids + b * NPTS;

    // Pass 1: 4 ids per thread (int4); first per id, counts, first valid.
    const int4 iv = ((const int4*)bid)[t];
    const int idr[4] = { iv.x, iv.y, iv.z, iv.w };
    int lv = 0;
    #pragma unroll
    for (int r = 0; r < 4; ++r) {
        const int i = 4 * t + r;
        if (idr[r] >= 0) {
            lv++;
            atomicMin(&s_j1, i);
            atomicMin(&s_first[idr[r]], i);
            atomicAdd(&s_count[idr[r]], 1);
        }
    }
    #pragma unroll
    for (int o = 16; o > 0; o >>= 1) lv += __shfl_xor_sync(0xFFFFFFFFu, lv, o);
    if (lane == 0) atomicAdd(&s_nvalid, lv);
    __syncthreads();
    if (t == 0) s_idj1 = (s_j1 < NPTS) ? bid[s_j1] : -2;
    __syncthreads();

    // Pass 2: second per id, j2, and grouped anchor-list append for my ids.
    const int idj1   = s_idj1;
    const int nvalid = s_nvalid;
    #pragma unroll
    for (int r = 0; r < 4; ++r) {
        const int i  = 4 * t + r;
        const int id = idr[r];
        if (id >= 0) {
            if (i != s_first[id]) atomicMin(&s_second[id], i);
            if (id != idj1)       atomicMin(&s_j2, i);
            if (id >= idbase && id < idbase + IDS_PER_BLK) {
                const int cmv = s_count[id];
                if (cmv >= 2 && nvalid > cmv) {          // ok(id)
                    const int c = id - idbase;
                    int off = 0;
                    #pragma unroll
                    for (int cc = 0; cc < IDS_PER_BLK; ++cc)
                        if (cc < c) off += s_count[idbase + cc];
                    const int k = atomicAdd(&s_sub[c], 1);
                    s_list[off + k] = i;
                }
            }
        }
    }
    __syncthreads();

    float w_tot = 0.0f;
    int   w_cnt = 0;

    const float4* __restrict__ base4 =
        (const float4*)(feats + (size_t)b * NPTS * DIM);
    const float eps = c_eps;

    const int m  = idbase + wid;       // this warp's id
    const int cm = s_count[m];
    const bool ok = (cm >= 2) && (nvalid > cm);

    if (ok) {
        const int first  = s_first[m];
        const int second = s_second[m];
        const int nidx   = (idj1 != m) ? s_j1 : s_j2;
        int off = 0;
        #pragma unroll
        for (int cc = 0; cc < IDS_PER_BLK; ++cc)
            if (cc < wid) off += s_count[idbase + cc];

        // Pos/neg rows -> registers; norms -> warp-uniform scalars.
        const float4* __restrict__ fP = base4 + (size_t)first * F4;
        const float4* __restrict__ fN = base4 + (size_t)nidx  * F4;
        const float4 P0 = fP[lane], P1 = fP[lane+32], P2 = fP[lane+64], P3 = fP[lane+96];
        const float4 N0 = fN[lane], N1 = fN[lane+32], N2 = fN[lane+64], N3 = fN[lane+96];
        float np = 0.0f, nn = 0.0f;
        NRM4(P0, np); NRM4(P1, np); NRM4(P2, np); NRM4(P3, np);
        NRM4(N0, nn); NRM4(N1, nn); NRM4(N2, nn); NRM4(N3, nn);
        #pragma unroll
        for (int o = 16; o > 0; o >>= 1) {
            np += __shfl_xor_sync(0xFFFFFFFFu, np, o);
            nn += __shfl_xor_sync(0xFFFFFFFFu, nn, o);
        }

        const uint32_t ancb =
            (uint32_t)__cvta_generic_to_shared(&s_anc[wid][0][0][0]);
        const int npairs = (cm + 1) / 2;

        // stage anchor list[off+idx] into (buf, slot)
        #define STAGE1(idx, bf, slot)                                          \
            do {                                                               \
                const float4* src_ = base4 + (size_t)s_list[off + (idx)] * F4; \
                const uint32_t d_ = ancb + (uint32_t)((bf) * 4096 +            \
                                    (slot) * 2048 + lane * 16);                \
                cp_async16(d_,        src_ + lane);                            \
                cp_async16(d_ + 512,  src_ + lane + 32);                       \
                cp_async16(d_ + 1024, src_ + lane + 64);                       \
                cp_async16(d_ + 1536, src_ + lane + 96);                       \
            } while (0)

        // prologue: pair 0 -> buf0, pair 1 -> buf1 (commit both groups)
        STAGE1(0, 0, 0);
        if (1 < cm) STAGE1(1, 0, 1);
        CP_COMMIT();
        if (npairs > 1) {
            STAGE1(2, 1, 0);
            if (3 < cm) STAGE1(3, 1, 1);
        }
        CP_COMMIT();

        int buf = 0;
        for (int pw = 0; pw < npairs; ++pw, buf ^= 1) {
            CP_WAIT1();                          // current buf ready
            const int iA = s_list[off + 2 * pw];
            const bool vB = (2 * pw + 1) < cm;
            const int iB = vB ? s_list[off + 2 * pw + 1] : iA;
            const float4* __restrict__ abA = s_anc[wid][buf][0];
            const float4* __restrict__ abB = s_anc[wid][buf][vB ? 1 : 0];

            float sapA = 0.0f, sanA = 0.0f, sapB = 0.0f, sanB = 0.0f;
            {
                const float4 aA0 = abA[lane],    aB0 = abB[lane];
                ACCK(aA0, P0, N0, sapA, sanA);   ACCK(aB0, P0, N0, sapB, sanB);
                const float4 aA1 = abA[lane+32], aB1 = abB[lane+32];
                ACCK(aA1, P1, N1, sapA, sanA);   ACCK(aB1, P1, N1, sapB, sanB);
                const float4 aA2 = abA[lane+64], aB2 = abB[lane+64];
                ACCK(aA2, P2, N2, sapA, sanA);   ACCK(aB2, P2, N2, sapB, sanB);
                const float4 aA3 = abA[lane+96], aB3 = abB[lane+96];
                ACCK(aA3, P3, N3, sapA, sanA);   ACCK(aB3, P3, N3, sapB, sanB);
            }

            float napA = np, napB = np;
            if (iA == first || (vB && iB == first)) {
                // rare warp-uniform path: that anchor pairs with `second`
                const float4* __restrict__ fS = base4 + (size_t)second * F4;
                const float4 S0 = fS[lane],    S1 = fS[lane+32];
                const float4 S2 = fS[lane+64], S3 = fS[lane+96];
                float ns = 0.0f;
                NRM4(S0, ns); NRM4(S1, ns); NRM4(S2, ns); NRM4(S3, ns);
                #pragma unroll
                for (int o = 16; o > 0; o >>= 1)
                    ns += __shfl_xor_sync(0xFFFFFFFFu, ns, o);
                const float4* __restrict__ ax = (iA == first) ? abA : abB;
                float s = 0.0f;
                ACCPK(ax[lane],    S0, s); ACCPK(ax[lane+32], S1, s);
                ACCPK(ax[lane+64], S2, s); ACCPK(ax[lane+96], S3, s);
                if (iA == first) { sapA = s; napA = ns; }
                else             { sapB = s; napB = ns; }
            }

            #pragma unroll
            for (int o = 16; o > 0; o >>= 1) {
                sapA += __shfl_xor_sync(0xFFFFFFFFu, sapA, o);
                sanA += __shfl_xor_sync(0xFFFFFFFFu, sanA, o);
                sapB += __shfl_xor_sync(0xFFFFFFFFu, sapB, o);
                sanB += __shfl_xor_sync(0xFFFFFFFFu, sanB, o);
            }
            if (lane == 0) {
                float per = sqrtf(sapA + napA) - sqrtf(sanA + nn) + c_margin;
                if (per > 0.0f) w_tot += per;
                w_cnt++;
                if (vB) {
                    per = sqrtf(sapB + napB) - sqrtf(sanB + nn) + c_margin;
                    if (per > 0.0f) w_tot += per;
                    w_cnt++;
                }
            }

            // stage pair pw+2 into the buffer just consumed
            const int na = 2 * (pw + 2);
            if (na < cm) {
                STAGE1(na, buf, 0);
                if (na + 1 < cm) STAGE1(na + 1, buf, 1);
            }
            CP_COMMIT();                         // one group per iteration
        }
        #undef STAGE1
    }

    if (lane == 0) {
        atomicAdd(&s_tot, w_tot);
        atomicAdd(&s_cnt, w_cnt);
    }
    __syncthreads();

    if (t == 0) {
        atomicAdd(&g_tot, s_tot);
        atomicAdd(&g_cntall, s_cnt);
        __threadfence();
        const unsigned int old = atomicAdd(&g_ticket, 1u);
        if (old == GRID - 1) {
            __threadfence();                 // see all blocks' adds
            const float T = g_tot;
            const int   C = g_cntall;
            const float loss = (C > 0) ? (T / (float)C) : 0.0f;
            if (out_size > 0) out[0] = loss; // tracking_loss
            if (out_size > 1) out[1] = loss; // loss_triplet
            if (out_size > 2) out[2] = 0.0f; // loss_id
            g_tot    = 0.0f;                 // reset for next graph replay
            g_cntall = 0;
            g_ticket = 0;
            __threadfence();
        }
    }
}

extern "C" void kernel_launch(void* const* d_in, const int* in_sizes, int n_in,
                              void* d_out, int out_size)
{
    const float* feats = (const float*)d_in[0];
    const int*   ids   = (const int*)d_in[1];
    float*       out   = (float*)d_out;

    dist_kernel<<<GRID, DTHREADS>>>(feats, ids, out, out_size);
}